// round 15
// baseline (speedup 1.0000x reference)
#include <cuda_runtime.h>
#include <cuda_fp16.h>
#include <math.h>
#include <stdint.h>

#define D    128
#define Bn   4
#define NSn  10000
#define NTn  10000
#define En   160000
#define Kc   16
#define LDS_T 136   // padded fp16 row (272B, 16B-aligned, ldmatrix conflict-free)
#define LDC   132   // padded fp32 C row

// ---------------- scratch ----------------
__device__ __half g_Ps  [Bn * NSn * D];   // src @ W_s2e   (fp16, L2-resident working set)
__device__ __half g_Pt  [Bn * NTn * D];   // tgt @ W_t2e   (fp16, L2-resident working set)
__device__ __half g_Ptt [Bn * NTn * D];   // tgt @ W_t2t   (fp16)
__device__ __half g_db  [Bn * En  * D];   // d_bond scratch (fp16, feeds reduce only)
__device__ float  g_red [Bn * NTn * D];
__device__ __half g_W[5 * D * D];   // 0=W_s2e 1=W_t2e 2=W_e2e 3=W_e2t 4=W_t2t (fp16)

// ---------------- PTX helpers ----------------
__device__ __forceinline__ uint32_t smem_u32(const void* p) {
    return (uint32_t)__cvta_generic_to_shared(p);
}
__device__ __forceinline__ void ldsm4(uint32_t a, uint32_t r[4]) {
    asm volatile("ldmatrix.sync.aligned.m8n8.x4.shared.b16 {%0,%1,%2,%3}, [%4];"
                 : "=r"(r[0]), "=r"(r[1]), "=r"(r[2]), "=r"(r[3]) : "r"(a));
}
__device__ __forceinline__ void ldsm4t(uint32_t a, uint32_t r[4]) {
    asm volatile("ldmatrix.sync.aligned.m8n8.x4.trans.shared.b16 {%0,%1,%2,%3}, [%4];"
                 : "=r"(r[0]), "=r"(r[1]), "=r"(r[2]), "=r"(r[3]) : "r"(a));
}
__device__ __forceinline__ void mma16816(float c[4], const uint32_t a[4],
                                         uint32_t b0, uint32_t b1) {
    asm volatile("mma.sync.aligned.m16n8k16.row.col.f32.f16.f16.f32 "
                 "{%0,%1,%2,%3},{%4,%5,%6,%7},{%8,%9},{%0,%1,%2,%3};"
                 : "+f"(c[0]), "+f"(c[1]), "+f"(c[2]), "+f"(c[3])
                 : "r"(a[0]), "r"(a[1]), "r"(a[2]), "r"(a[3]), "r"(b0), "r"(b1));
}
__device__ __forceinline__ void cp16(uint32_t dst, const void* src) {
    asm volatile("cp.async.cg.shared.global [%0], [%1], 16;" :: "r"(dst), "l"(src));
}
__device__ __forceinline__ void cp_commit() { asm volatile("cp.async.commit_group;"); }
__device__ __forceinline__ void cp_wait0()  { asm volatile("cp.async.wait_group 0;"); }
__device__ __forceinline__ void pref_l2(const void* p) {
    asm volatile("prefetch.global.L2 [%0];" :: "l"(p));
}
__device__ __forceinline__ float silu_f(float x) { return x / (1.0f + __expf(-x)); }

// ---------------- weight fp16 convert ----------------
__global__ __launch_bounds__(256) void prep_w_kernel(const float* __restrict__ W0,
                                                     const float* __restrict__ W1,
                                                     const float* __restrict__ W2,
                                                     const float* __restrict__ W3,
                                                     const float* __restrict__ W4) {
    int i = blockIdx.x * 256 + threadIdx.x;
    int w = i >> 14, j = i & (D * D - 1);
    const float* W = (w == 0) ? W0 : (w == 1) ? W1 : (w == 2) ? W2 : (w == 3) ? W3 : W4;
    g_W[i] = __float2half_rn(W[j]);
}

// ---------------- tile loads ----------------
__device__ __forceinline__ void load_W_cp(__half* Ws, int widx, int tid) {
    const __half* gw = g_W + widx * D * D;
    uint32_t dw = smem_u32(Ws);
    #pragma unroll
    for (int i = tid; i < D * 16; i += 256) {
        int r = i >> 4, c = (i & 15) * 8;
        cp16(dw + (uint32_t)(r * LDS_T + c) * 2, gw + r * D + c);
    }
}
// fp32 -> fp16 smem image; streamed read-once input (evict-first); optional passthrough
__device__ __forceinline__ void load_X_f16(__half* Xs, const float* __restrict__ Xg,
                                           float* __restrict__ cp, int tid) {
    #pragma unroll
    for (int i = tid; i < 64 * 32; i += 256) {
        int r = i >> 5, c = (i & 31) * 4;
        float4 v = __ldcs((const float4*)(Xg + (size_t)r * D + c));
        if (cp) __stcs((float4*)(cp + (size_t)r * D + c), v);
        __half2 a = __floats2half2_rn(v.x, v.y);
        __half2 b = __floats2half2_rn(v.z, v.w);
        *(uint32_t*)(Xs + r * LDS_T + c)     = *(uint32_t*)&a;
        *(uint32_t*)(Xs + r * LDS_T + c + 2) = *(uint32_t*)&b;
    }
}

// ---------------- fp16 single-MMA GEMM core: 64x128 tile, 8 warps (4 rg x 2 cg) ----------------
#define KOFF ((uint32_t)(16 * LDS_T * 2))

__device__ __forceinline__ void gemm_mma64(const __half* Xs, const __half* Ws,
                                           int tid, float acc[8][4]) {
    int lane = tid & 31, w = tid >> 5;
    int rg = (w & 3) * 16, cg = (w >> 2) * 64;
    #pragma unroll
    for (int i = 0; i < 8; i++)
        #pragma unroll
        for (int j = 0; j < 4; j++) acc[i][j] = 0.0f;
    int l7 = lane & 7, lm = lane >> 3;
    int a_cad = (lm >> 1) << 3;
    uint32_t aA = smem_u32(Xs + (rg + l7 + ((lm & 1) << 3)) * LDS_T + a_cad);
    int b_krow = l7 + ((lm & 1) << 3);
    uint32_t bB[4];
    #pragma unroll
    for (int nr = 0; nr < 4; nr++) {
        int col = cg + nr * 16 + a_cad;
        bB[nr] = smem_u32(Ws + b_krow * LDS_T + col);
    }
    #pragma unroll
    for (int k = 0; k < 8; k++) {
        uint32_t A[4];
        ldsm4(aA + (uint32_t)k * 32, A);
        #pragma unroll
        for (int nr = 0; nr < 4; nr++) {
            uint32_t B[4];
            ldsm4t(bB[nr] + (uint32_t)k * KOFF, B);
            mma16816(acc[2 * nr],     A, B[0], B[1]);
            mma16816(acc[2 * nr + 1], A, B[2], B[3]);
        }
    }
}

__device__ __forceinline__ void stage_acc(float* Cs, const float acc[8][4], int tid) {
    int lane = tid & 31, w = tid >> 5;
    int rg = (w & 3) * 16, cg = (w >> 2) * 64;
    int gid = lane >> 2, tid4 = lane & 3;
    #pragma unroll
    for (int nt = 0; nt < 8; nt++) {
        int col = cg + nt * 8 + tid4 * 2;
        int row = rg + gid;
        *(float2*)(Cs + row * LDC + col)       = make_float2(acc[nt][0], acc[nt][1]);
        *(float2*)(Cs + (row + 8) * LDC + col) = make_float2(acc[nt][2], acc[nt][3]);
    }
}
__device__ __forceinline__ void silu_ln(float v[4], const float gg[4], const float bb[4],
                                        float out[4]) {
    #pragma unroll
    for (int c = 0; c < 4; c++) v[c] = silu_f(v[c]);
    float s1 = v[0] + v[1] + v[2] + v[3];
    float s2 = v[0]*v[0] + v[1]*v[1] + v[2]*v[2] + v[3]*v[3];
    #pragma unroll
    for (int o = 16; o > 0; o >>= 1) {
        s1 += __shfl_xor_sync(0xFFFFFFFFu, s1, o);
        s2 += __shfl_xor_sync(0xFFFFFFFFu, s2, o);
    }
    float m   = s1 * (1.0f / D);
    float var = fmaxf(s2 * (1.0f / D) - m * m, 0.0f);
    float rs  = rsqrtf(var + 1e-5f);
    #pragma unroll
    for (int c = 0; c < 4; c++) out[c] = (v[c] - m) * rs * gg[c] + bb[c];
}

// smem: [Ws 128x136][Xs 64x136] fp16; Cs (64x132 fp32) overlays Ws only
#define SM_SINGLE ((D * LDS_T + 64 * LDS_T) * 2)
// bond adds sG/sB (128 floats each) after Xs
#define SM_BOND   (SM_SINGLE + 2 * D * 4)

// ---------------- merged projection kernel: 3 GEMM jobs, fp16 outputs ----------------
// job 0: Ps = src@W_s2e (+ passthrough src->out1) ; job 1: Pt = tgt@W_t2e ; job 2: Ptt = tgt@W_t2t
__global__ __launch_bounds__(256, 3) void proj_kernel(const float* __restrict__ src,
                                                      const float* __restrict__ tgt,
                                                      float* __restrict__ out1) {
    extern __shared__ char sm[];
    __half* Ws = (__half*)sm;
    __half* Xs = Ws + D * LDS_T;
    float* Cs = (float*)sm;           // overlays Ws after MMA
    int tid = threadIdx.x;
    int job = blockIdx.x / 625;
    int blk = blockIdx.x - job * 625;
    const float* X = (job == 0) ? src : tgt;
    int widx = (job == 0) ? 0 : (job == 1) ? 1 : 4;
    __half* outp = (job == 0) ? g_Ps : (job == 1) ? g_Pt : g_Ptt;
    int row0 = blk * 64;
    load_W_cp(Ws, widx, tid);
    cp_commit();
    load_X_f16(Xs, X + (size_t)row0 * D,
               (job == 0) ? (out1 + (size_t)row0 * D) : (float*)0, tid);
    cp_wait0();
    __syncthreads();
    float acc[8][4];
    gemm_mma64(Xs, Ws, tid, acc);
    __syncthreads();
    stage_acc(Cs, acc, tid);
    __syncthreads();
    int tx = tid & 31, ty = tid >> 5;
    #pragma unroll
    for (int r = 0; r < 8; r++) {
        float4 v = *(float4*)(Cs + (ty * 8 + r) * LDC + tx * 4);
        __half2 a = __floats2half2_rn(v.x, v.y);
        __half2 b = __floats2half2_rn(v.z, v.w);
        uint2 pk = make_uint2(*(uint32_t*)&a, *(uint32_t*)&b);
        *(uint2*)(outp + (size_t)(row0 + ty * 8 + r) * D + tx * 4) = pk;   // keep cached
    }
}

// ---------------- kernel 3: d_bond = LN(silu(bond@W_e2e + gather(Ps) + gather(Pt))) ----------------
__global__ __launch_bounds__(256, 4) void bond_kernel(const float* __restrict__ bond,
                                                      const float* __restrict__ g1,
                                                      const float* __restrict__ b1,
                                                      const int* __restrict__ src_order,
                                                      const int* __restrict__ tgt_order,
                                                      float* __restrict__ out0) {
    extern __shared__ char sm[];
    __half* Ws = (__half*)sm;
    __half* Xs = Ws + D * LDS_T;
    float* sG = (float*)(Xs + 64 * LDS_T);
    float* sB = sG + D;
    float* Cs = (float*)sm;           // overlays Ws only; Xs/sG/sB stay live
    int tid = threadIdx.x;
    int tx = tid & 31, ty = tid >> 5;
    int row0 = blockIdx.x * 64;           // global row in [0, B*E)
    int b    = row0 / En;                 // tile never crosses batch (E % 64 == 0)
    int ebase = row0 - b * En;
    const __half* PsB = g_Ps + (size_t)b * NSn * D;
    const __half* PtB = g_Pt + (size_t)b * NTn * D;

    load_W_cp(Ws, 2, tid);                // W_e2e (async)
    cp_commit();
    load_X_f16(Xs, bond + (size_t)row0 * D, (float*)0, tid);
    if (tid < D) { sG[tid] = g1[tid]; sB[tid] = b1[tid]; }

    // pre-MMA: prefetch Ps/Pt gather sectors into L2 (fp16 rows = 2 x 128B sectors)
    {
        int rr = tx >> 2;                 // 8 rows per warp
        int h  = (tx & 1) * 64;           // 2 sectors of 64 halves
        int e = ebase + ty * 8 + rr;
        if (tx & 2) pref_l2(PtB + (size_t)tgt_order[e] * D + h);
        else        pref_l2(PsB + (size_t)src_order[e] * D + h);
    }

    cp_wait0();
    __syncthreads();
    float acc[8][4];
    gemm_mma64(Xs, Ws, tid, acc);
    __syncthreads();
    stage_acc(Cs, acc, tid);
    __syncthreads();

    #pragma unroll
    for (int r = 0; r < 8; r++) {
        int row = row0 + ty * 8 + r;
        int e   = ebase + ty * 8 + r;
        int so  = src_order[e];
        int to  = tgt_order[e];
        float4 cv = *(float4*)(Cs + (ty * 8 + r) * LDC + tx * 4);
        uint2 pp = *(const uint2*)(PsB + (size_t)so * D + tx * 4);
        uint2 qq = *(const uint2*)(PtB + (size_t)to * D + tx * 4);
        __half2 p0 = *(__half2*)&pp.x, p1 = *(__half2*)&pp.y;
        __half2 q0 = *(__half2*)&qq.x, q1 = *(__half2*)&qq.y;
        float v[4];
        v[0] = cv.x + __half2float(p0.x) + __half2float(q0.x);
        v[1] = cv.y + __half2float(p0.y) + __half2float(q0.y);
        v[2] = cv.z + __half2float(p1.x) + __half2float(q1.x);
        v[3] = cv.w + __half2float(p1.y) + __half2float(q1.y);
        float gg[4] = {sG[tx * 4], sG[tx * 4 + 1], sG[tx * 4 + 2], sG[tx * 4 + 3]};
        float bb[4] = {sB[tx * 4], sB[tx * 4 + 1], sB[tx * 4 + 2], sB[tx * 4 + 3]};
        float d[4];
        silu_ln(v, gg, bb, d);
        // x for the residual read back from the fp16 smem image (no DRAM re-read)
        __half2 x01 = *(const __half2*)(Xs + (ty * 8 + r) * LDS_T + tx * 4);
        __half2 x23 = *(const __half2*)(Xs + (ty * 8 + r) * LDS_T + tx * 4 + 2);
        float4 o0 = {__half2float(x01.x) + d[0], __half2float(x01.y) + d[1],
                     __half2float(x23.x) + d[2], __half2float(x23.y) + d[3]};
        // streamed outputs: evict-first so Ps/Pt stay L2-resident
        __half2 d01 = __floats2half2_rn(d[0], d[1]);
        __half2 d23 = __floats2half2_rn(d[2], d[3]);
        uint2 dpk = make_uint2(*(uint32_t*)&d01, *(uint32_t*)&d23);
        __stcs((uint2*)(g_db + (size_t)row * D + tx * 4), dpk);
        __stcs((float4*)(out0 + (size_t)row * D + tx * 4), o0);
    }
}

// ---------------- kernel 4: bond_reduce = mean_k(coef * d_bond[edge_order]) ----------------
// one warp per node; lane covers 4 halves (cols lane*4 .. lane*4+3)
__global__ __launch_bounds__(256) void reduce_kernel(const int* __restrict__ edge_order,
                                                     const float* __restrict__ coef) {
    int tid  = threadIdx.x;
    int lane = tid & 31;
    int node = (blockIdx.x * blockDim.x + tid) >> 5;
    int b = node / NTn;
    int t = node - b * NTn;
    int   e_l = 0;
    float c_l = 0.0f;
    if (lane < Kc) {
        e_l = edge_order[t * Kc + lane];
        c_l = coef[t * Kc + lane];
    }
    float4 acc = {0.f, 0.f, 0.f, 0.f};
    #pragma unroll
    for (int k = 0; k < Kc; k++) {
        int   e = __shfl_sync(0xFFFFFFFFu, e_l, k);
        float c = __shfl_sync(0xFFFFFFFFu, c_l, k);
        uint2 pk = __ldcs((const uint2*)(g_db + ((size_t)b * En + e) * D + lane * 4));
        __half2 h0 = *(__half2*)&pk.x;
        __half2 h1 = *(__half2*)&pk.y;
        acc.x += c * __half2float(h0.x);
        acc.y += c * __half2float(h0.y);
        acc.z += c * __half2float(h1.x);
        acc.w += c * __half2float(h1.y);
    }
    const float inv = 1.0f / Kc;
    acc.x *= inv; acc.y *= inv; acc.z *= inv; acc.w *= inv;
    *(float4*)(g_red + (size_t)node * D + lane * 4) = acc;   // re-read by tgt: keep cached
}

// ---------------- kernel 5: d_tgt = LN(silu(red@W_e2t + Ptt)) ; out = tgt + d_tgt ----------------
__global__ __launch_bounds__(256, 3) void tgt_kernel(const float* __restrict__ tgt,
                                                     const float* __restrict__ g2,
                                                     const float* __restrict__ b2,
                                                     float* __restrict__ out2) {
    extern __shared__ char sm[];
    __half* Ws = (__half*)sm;
    __half* Xs = Ws + D * LDS_T;
    float* Cs = (float*)sm;
    int tid = threadIdx.x;
    int row0 = blockIdx.x * 64;
    load_W_cp(Ws, 3, tid);
    cp_commit();
    load_X_f16(Xs, g_red + (size_t)row0 * D, (float*)0, tid);
    cp_wait0();
    __syncthreads();
    float acc[8][4];
    gemm_mma64(Xs, Ws, tid, acc);
    __syncthreads();
    stage_acc(Cs, acc, tid);
    __syncthreads();

    int tx = tid & 31, ty = tid >> 5;
    float gg[4], bb[4];
    #pragma unroll
    for (int c = 0; c < 4; c++) { gg[c] = g2[tx * 4 + c]; bb[c] = b2[tx * 4 + c]; }
    #pragma unroll
    for (int r = 0; r < 8; r++) {
        int row = row0 + ty * 8 + r;
        float4 cv = *(float4*)(Cs + (ty * 8 + r) * LDC + tx * 4);
        uint2 pp = *(const uint2*)(g_Ptt + (size_t)row * D + tx * 4);
        __half2 p0 = *(__half2*)&pp.x, p1 = *(__half2*)&pp.y;
        float v[4];
        v[0] = cv.x + __half2float(p0.x);
        v[1] = cv.y + __half2float(p0.y);
        v[2] = cv.z + __half2float(p1.x);
        v[3] = cv.w + __half2float(p1.y);
        float d[4];
        silu_ln(v, gg, bb, d);
        float4 tin = __ldcs((const float4*)(tgt + (size_t)row * D + tx * 4));
        float4 o2 = {tin.x + d[0], tin.y + d[1], tin.z + d[2], tin.w + d[3]};
        __stcs((float4*)(out2 + (size_t)row * D + tx * 4), o2);
    }
}

// ---------------- launch ----------------
extern "C" void kernel_launch(void* const* d_in, const int* in_sizes, int n_in,
                              void* d_out, int out_size) {
    const float* bond  = (const float*)d_in[0];
    const float* src   = (const float*)d_in[1];
    const float* tgt   = (const float*)d_in[2];
    const float* W_s2e = (const float*)d_in[3];
    const float* W_t2e = (const float*)d_in[4];
    const float* W_e2e = (const float*)d_in[5];
    const float* ln1_g = (const float*)d_in[6];
    const float* ln1_b = (const float*)d_in[7];
    const float* W_e2t = (const float*)d_in[8];
    const float* W_t2t = (const float*)d_in[9];
    const float* ln2_g = (const float*)d_in[10];
    const float* ln2_b = (const float*)d_in[11];
    const float* coef  = (const float*)d_in[12];
    const int*   so    = (const int*)d_in[13];
    const int*   to    = (const int*)d_in[14];
    const int*   eo    = (const int*)d_in[15];

    float* out  = (float*)d_out;
    float* out0 = out;                                   // bond + d_bond   [B,E,D]
    float* out1 = out0 + (size_t)Bn * En * D;            // src passthrough [B,NS,D]
    float* out2 = out1 + (size_t)Bn * NSn * D;           // tgt + d_tgt     [B,NT,D]

    cudaFuncSetAttribute(proj_kernel, cudaFuncAttributeMaxDynamicSharedMemorySize, SM_SINGLE);
    cudaFuncSetAttribute(bond_kernel, cudaFuncAttributeMaxDynamicSharedMemorySize, SM_BOND);
    cudaFuncSetAttribute(tgt_kernel,  cudaFuncAttributeMaxDynamicSharedMemorySize, SM_SINGLE);

    prep_w_kernel<<<320, 256>>>(W_s2e, W_t2e, W_e2e, W_e2t, W_t2t);

    // three projection GEMMs + fused src passthrough
    proj_kernel<<<3 * 625, 256, SM_SINGLE>>>(src, tgt, out1);

    bond_kernel<<<(Bn * En) / 64, 256, SM_BOND>>>(bond, ln1_g, ln1_b, so, to, out0);

    reduce_kernel<<<(Bn * NTn) / 8, 256>>>(eo, coef);

    tgt_kernel<<<(Bn * NTn) / 64, 256, SM_SINGLE>>>(tgt, ln2_g, ln2_b, out2);
}

// round 16
// speedup vs baseline: 1.0546x; 1.0546x over previous
#include <cuda_runtime.h>
#include <cuda_fp16.h>
#include <math.h>
#include <stdint.h>

#define D    128
#define Bn   4
#define NSn  10000
#define NTn  10000
#define En   160000
#define Kc   16
#define LDS_T 136   // padded fp16 row (272B, 16B-aligned, ldmatrix conflict-free)
#define LDC   132   // padded fp32 C row

// ---------------- scratch ----------------
__device__ __half g_Ps  [Bn * NSn * D];   // src @ W_s2e   (fp16)
__device__ __half g_Pt  [Bn * NTn * D];   // tgt @ W_t2e   (fp16)
__device__ __half g_Ptt [Bn * NTn * D];   // tgt @ W_t2t   (fp16)
__device__ __half g_db  [Bn * En  * D];   // d_bond scratch (fp16, feeds reduce only)
__device__ __half g_red [Bn * NTn * D];   // bond_reduce (fp16, feeds tgt GEMM only)
__device__ __half g_W[5 * D * D];   // 0=W_s2e 1=W_t2e 2=W_e2e 3=W_e2t 4=W_t2t (fp16)

// ---------------- PTX helpers ----------------
__device__ __forceinline__ uint32_t smem_u32(const void* p) {
    return (uint32_t)__cvta_generic_to_shared(p);
}
__device__ __forceinline__ void ldsm4(uint32_t a, uint32_t r[4]) {
    asm volatile("ldmatrix.sync.aligned.m8n8.x4.shared.b16 {%0,%1,%2,%3}, [%4];"
                 : "=r"(r[0]), "=r"(r[1]), "=r"(r[2]), "=r"(r[3]) : "r"(a));
}
__device__ __forceinline__ void ldsm4t(uint32_t a, uint32_t r[4]) {
    asm volatile("ldmatrix.sync.aligned.m8n8.x4.trans.shared.b16 {%0,%1,%2,%3}, [%4];"
                 : "=r"(r[0]), "=r"(r[1]), "=r"(r[2]), "=r"(r[3]) : "r"(a));
}
__device__ __forceinline__ void mma16816(float c[4], const uint32_t a[4],
                                         uint32_t b0, uint32_t b1) {
    asm volatile("mma.sync.aligned.m16n8k16.row.col.f32.f16.f16.f32 "
                 "{%0,%1,%2,%3},{%4,%5,%6,%7},{%8,%9},{%0,%1,%2,%3};"
                 : "+f"(c[0]), "+f"(c[1]), "+f"(c[2]), "+f"(c[3])
                 : "r"(a[0]), "r"(a[1]), "r"(a[2]), "r"(a[3]), "r"(b0), "r"(b1));
}
__device__ __forceinline__ void cp16(uint32_t dst, const void* src) {
    asm volatile("cp.async.cg.shared.global [%0], [%1], 16;" :: "r"(dst), "l"(src));
}
__device__ __forceinline__ void cp_commit() { asm volatile("cp.async.commit_group;"); }
__device__ __forceinline__ void cp_wait0()  { asm volatile("cp.async.wait_group 0;"); }
__device__ __forceinline__ void pref_l2(const void* p) {
    asm volatile("prefetch.global.L2 [%0];" :: "l"(p));
}
__device__ __forceinline__ float silu_f(float x) { return x / (1.0f + __expf(-x)); }

// ---------------- weight fp16 convert ----------------
__global__ __launch_bounds__(256) void prep_w_kernel(const float* __restrict__ W0,
                                                     const float* __restrict__ W1,
                                                     const float* __restrict__ W2,
                                                     const float* __restrict__ W3,
                                                     const float* __restrict__ W4) {
    int i = blockIdx.x * 256 + threadIdx.x;
    int w = i >> 14, j = i & (D * D - 1);
    const float* W = (w == 0) ? W0 : (w == 1) ? W1 : (w == 2) ? W2 : (w == 3) ? W3 : W4;
    g_W[i] = __float2half_rn(W[j]);
}

// ---------------- tile loads ----------------
__device__ __forceinline__ void load_W_cp(__half* Ws, int widx, int tid) {
    const __half* gw = g_W + widx * D * D;
    uint32_t dw = smem_u32(Ws);
    #pragma unroll
    for (int i = tid; i < D * 16; i += 256) {
        int r = i >> 4, c = (i & 15) * 8;
        cp16(dw + (uint32_t)(r * LDS_T + c) * 2, gw + r * D + c);
    }
}
// fp16 global rows -> padded fp16 smem image via cp.async (64 rows)
__device__ __forceinline__ void load_Xh_cp(__half* Xs, const __half* __restrict__ Xg, int tid) {
    uint32_t dx = smem_u32(Xs);
    #pragma unroll
    for (int i = tid; i < 64 * 16; i += 256) {
        int r = i >> 4, c = (i & 15) * 8;
        cp16(dx + (uint32_t)(r * LDS_T + c) * 2, Xg + (size_t)r * D + c);
    }
}
// fp32 -> fp16 smem image; optional passthrough copy of the fp32 rows to `cp`
__device__ __forceinline__ void load_X_f16(__half* Xs, const float* __restrict__ Xg,
                                           float* __restrict__ cp, int tid) {
    #pragma unroll
    for (int i = tid; i < 64 * 32; i += 256) {
        int r = i >> 5, c = (i & 31) * 4;
        float4 v = *(const float4*)(Xg + (size_t)r * D + c);
        if (cp) *(float4*)(cp + (size_t)r * D + c) = v;
        __half2 a = __floats2half2_rn(v.x, v.y);
        __half2 b = __floats2half2_rn(v.z, v.w);
        *(uint32_t*)(Xs + r * LDS_T + c)     = *(uint32_t*)&a;
        *(uint32_t*)(Xs + r * LDS_T + c + 2) = *(uint32_t*)&b;
    }
}

// ---------------- fp16 single-MMA GEMM core: 64x128 tile, 8 warps (4 rg x 2 cg) ----------------
#define KOFF ((uint32_t)(16 * LDS_T * 2))

__device__ __forceinline__ void gemm_mma64(const __half* Xs, const __half* Ws,
                                           int tid, float acc[8][4]) {
    int lane = tid & 31, w = tid >> 5;
    int rg = (w & 3) * 16, cg = (w >> 2) * 64;
    #pragma unroll
    for (int i = 0; i < 8; i++)
        #pragma unroll
        for (int j = 0; j < 4; j++) acc[i][j] = 0.0f;
    int l7 = lane & 7, lm = lane >> 3;
    int a_cad = (lm >> 1) << 3;
    uint32_t aA = smem_u32(Xs + (rg + l7 + ((lm & 1) << 3)) * LDS_T + a_cad);
    int b_krow = l7 + ((lm & 1) << 3);
    uint32_t bB[4];
    #pragma unroll
    for (int nr = 0; nr < 4; nr++) {
        int col = cg + nr * 16 + a_cad;
        bB[nr] = smem_u32(Ws + b_krow * LDS_T + col);
    }
    #pragma unroll
    for (int k = 0; k < 8; k++) {
        uint32_t A[4];
        ldsm4(aA + (uint32_t)k * 32, A);
        #pragma unroll
        for (int nr = 0; nr < 4; nr++) {
            uint32_t B[4];
            ldsm4t(bB[nr] + (uint32_t)k * KOFF, B);
            mma16816(acc[2 * nr],     A, B[0], B[1]);
            mma16816(acc[2 * nr + 1], A, B[2], B[3]);
        }
    }
}

__device__ __forceinline__ void stage_acc(float* Cs, const float acc[8][4], int tid) {
    int lane = tid & 31, w = tid >> 5;
    int rg = (w & 3) * 16, cg = (w >> 2) * 64;
    int gid = lane >> 2, tid4 = lane & 3;
    #pragma unroll
    for (int nt = 0; nt < 8; nt++) {
        int col = cg + nt * 8 + tid4 * 2;
        int row = rg + gid;
        *(float2*)(Cs + row * LDC + col)       = make_float2(acc[nt][0], acc[nt][1]);
        *(float2*)(Cs + (row + 8) * LDC + col) = make_float2(acc[nt][2], acc[nt][3]);
    }
}
__device__ __forceinline__ void silu_ln(float v[4], const float gg[4], const float bb[4],
                                        float out[4]) {
    #pragma unroll
    for (int c = 0; c < 4; c++) v[c] = silu_f(v[c]);
    float s1 = v[0] + v[1] + v[2] + v[3];
    float s2 = v[0]*v[0] + v[1]*v[1] + v[2]*v[2] + v[3]*v[3];
    #pragma unroll
    for (int o = 16; o > 0; o >>= 1) {
        s1 += __shfl_xor_sync(0xFFFFFFFFu, s1, o);
        s2 += __shfl_xor_sync(0xFFFFFFFFu, s2, o);
    }
    float m   = s1 * (1.0f / D);
    float var = fmaxf(s2 * (1.0f / D) - m * m, 0.0f);
    float rs  = rsqrtf(var + 1e-5f);
    #pragma unroll
    for (int c = 0; c < 4; c++) out[c] = (v[c] - m) * rs * gg[c] + bb[c];
}

// smem: [Ws 128x136][Xs 64x136] fp16; Cs (64x132 fp32) overlays Ws only
#define SM_SINGLE ((D * LDS_T + 64 * LDS_T) * 2)
// bond adds sG/sB (128 floats each) after Xs
#define SM_BOND   (SM_SINGLE + 2 * D * 4)

// ---------------- merged projection kernel: 3 GEMM jobs, fp16 outputs ----------------
// job 0: Ps = src@W_s2e (+ passthrough src->out1) ; job 1: Pt = tgt@W_t2e ; job 2: Ptt = tgt@W_t2t
__global__ __launch_bounds__(256, 3) void proj_kernel(const float* __restrict__ src,
                                                      const float* __restrict__ tgt,
                                                      float* __restrict__ out1) {
    extern __shared__ char sm[];
    __half* Ws = (__half*)sm;
    __half* Xs = Ws + D * LDS_T;
    float* Cs = (float*)sm;           // overlays Ws after MMA
    int tid = threadIdx.x;
    int job = blockIdx.x / 625;
    int blk = blockIdx.x - job * 625;
    const float* X = (job == 0) ? src : tgt;
    int widx = (job == 0) ? 0 : (job == 1) ? 1 : 4;
    __half* outp = (job == 0) ? g_Ps : (job == 1) ? g_Pt : g_Ptt;
    int row0 = blk * 64;
    load_W_cp(Ws, widx, tid);
    cp_commit();
    load_X_f16(Xs, X + (size_t)row0 * D,
               (job == 0) ? (out1 + (size_t)row0 * D) : (float*)0, tid);
    cp_wait0();
    __syncthreads();
    float acc[8][4];
    gemm_mma64(Xs, Ws, tid, acc);
    __syncthreads();
    stage_acc(Cs, acc, tid);
    __syncthreads();
    int tx = tid & 31, ty = tid >> 5;
    #pragma unroll
    for (int r = 0; r < 8; r++) {
        float4 v = *(float4*)(Cs + (ty * 8 + r) * LDC + tx * 4);
        __half2 a = __floats2half2_rn(v.x, v.y);
        __half2 b = __floats2half2_rn(v.z, v.w);
        uint2 pk = make_uint2(*(uint32_t*)&a, *(uint32_t*)&b);
        *(uint2*)(outp + (size_t)(row0 + ty * 8 + r) * D + tx * 4) = pk;
    }
}

// ---------------- kernel 3: d_bond = LN(silu(bond@W_e2e + gather(Ps) + gather(Pt))) ----------------
__global__ __launch_bounds__(256, 4) void bond_kernel(const float* __restrict__ bond,
                                                      const float* __restrict__ g1,
                                                      const float* __restrict__ b1,
                                                      const int* __restrict__ src_order,
                                                      const int* __restrict__ tgt_order,
                                                      float* __restrict__ out0) {
    extern __shared__ char sm[];
    __half* Ws = (__half*)sm;
    __half* Xs = Ws + D * LDS_T;
    float* sG = (float*)(Xs + 64 * LDS_T);
    float* sB = sG + D;
    float* Cs = (float*)sm;           // overlays Ws only; Xs/sG/sB stay live
    int tid = threadIdx.x;
    int tx = tid & 31, ty = tid >> 5;
    int row0 = blockIdx.x * 64;           // global row in [0, B*E)
    int b    = row0 / En;                 // tile never crosses batch (E % 64 == 0)
    int ebase = row0 - b * En;
    const __half* PsB = g_Ps + (size_t)b * NSn * D;
    const __half* PtB = g_Pt + (size_t)b * NTn * D;

    load_W_cp(Ws, 2, tid);                // W_e2e (async)
    cp_commit();
    load_X_f16(Xs, bond + (size_t)row0 * D, (float*)0, tid);
    if (tid < D) { sG[tid] = g1[tid]; sB[tid] = b1[tid]; }

    // pre-MMA: prefetch Ps/Pt gather sectors into L2 (fp16 rows = 2 x 128B sectors)
    {
        int rr = tx >> 2;                 // 8 rows per warp
        int h  = (tx & 1) * 64;           // 2 sectors of 64 halves
        int e = ebase + ty * 8 + rr;
        if (tx & 2) pref_l2(PtB + (size_t)tgt_order[e] * D + h);
        else        pref_l2(PsB + (size_t)src_order[e] * D + h);
    }

    cp_wait0();
    __syncthreads();
    float acc[8][4];
    gemm_mma64(Xs, Ws, tid, acc);
    __syncthreads();
    stage_acc(Cs, acc, tid);
    __syncthreads();

    #pragma unroll
    for (int r = 0; r < 8; r++) {
        int row = row0 + ty * 8 + r;
        int e   = ebase + ty * 8 + r;
        int so  = src_order[e];
        int to  = tgt_order[e];
        float4 cv = *(float4*)(Cs + (ty * 8 + r) * LDC + tx * 4);
        uint2 pp = *(const uint2*)(PsB + (size_t)so * D + tx * 4);
        uint2 qq = *(const uint2*)(PtB + (size_t)to * D + tx * 4);
        __half2 p0 = *(__half2*)&pp.x, p1 = *(__half2*)&pp.y;
        __half2 q0 = *(__half2*)&qq.x, q1 = *(__half2*)&qq.y;
        float v[4];
        v[0] = cv.x + __half2float(p0.x) + __half2float(q0.x);
        v[1] = cv.y + __half2float(p0.y) + __half2float(q0.y);
        v[2] = cv.z + __half2float(p1.x) + __half2float(q1.x);
        v[3] = cv.w + __half2float(p1.y) + __half2float(q1.y);
        float gg[4] = {sG[tx * 4], sG[tx * 4 + 1], sG[tx * 4 + 2], sG[tx * 4 + 3]};
        float bb[4] = {sB[tx * 4], sB[tx * 4 + 1], sB[tx * 4 + 2], sB[tx * 4 + 3]};
        float d[4];
        silu_ln(v, gg, bb, d);
        // x for the residual read back from the fp16 smem image (no DRAM re-read)
        __half2 x01 = *(const __half2*)(Xs + (ty * 8 + r) * LDS_T + tx * 4);
        __half2 x23 = *(const __half2*)(Xs + (ty * 8 + r) * LDS_T + tx * 4 + 2);
        float4 o0 = {__half2float(x01.x) + d[0], __half2float(x01.y) + d[1],
                     __half2float(x23.x) + d[2], __half2float(x23.y) + d[3]};
        // d_bond scratch in fp16 (coalesced 8B/lane)
        __half2 d01 = __floats2half2_rn(d[0], d[1]);
        __half2 d23 = __floats2half2_rn(d[2], d[3]);
        uint2 dpk = make_uint2(*(uint32_t*)&d01, *(uint32_t*)&d23);
        *(uint2*)(g_db + (size_t)row * D + tx * 4) = dpk;
        *(float4*)(out0 + (size_t)row * D + tx * 4) = o0;
    }
}

// ---------------- kernel 4: bond_reduce = mean_k(coef * d_bond[edge_order]) ----------------
// one warp per node; lane covers 4 halves (cols lane*4 .. lane*4+3); fp16 output
__global__ __launch_bounds__(256) void reduce_kernel(const int* __restrict__ edge_order,
                                                     const float* __restrict__ coef) {
    int tid  = threadIdx.x;
    int lane = tid & 31;
    int node = (blockIdx.x * blockDim.x + tid) >> 5;
    int b = node / NTn;
    int t = node - b * NTn;
    int   e_l = 0;
    float c_l = 0.0f;
    if (lane < Kc) {
        e_l = edge_order[t * Kc + lane];
        c_l = coef[t * Kc + lane];
    }
    float4 acc = {0.f, 0.f, 0.f, 0.f};
    #pragma unroll
    for (int k = 0; k < Kc; k++) {
        int   e = __shfl_sync(0xFFFFFFFFu, e_l, k);
        float c = __shfl_sync(0xFFFFFFFFu, c_l, k);
        uint2 pk = *(const uint2*)(g_db + ((size_t)b * En + e) * D + lane * 4);
        __half2 h0 = *(__half2*)&pk.x;
        __half2 h1 = *(__half2*)&pk.y;
        acc.x += c * __half2float(h0.x);
        acc.y += c * __half2float(h0.y);
        acc.z += c * __half2float(h1.x);
        acc.w += c * __half2float(h1.y);
    }
    const float inv = 1.0f / Kc;
    __half2 r01 = __floats2half2_rn(acc.x * inv, acc.y * inv);
    __half2 r23 = __floats2half2_rn(acc.z * inv, acc.w * inv);
    uint2 pk = make_uint2(*(uint32_t*)&r01, *(uint32_t*)&r23);
    *(uint2*)(g_red + (size_t)node * D + lane * 4) = pk;
}

// ---------------- kernel 5: d_tgt = LN(silu(red@W_e2t + Ptt)) ; out = tgt + d_tgt ----------------
__global__ __launch_bounds__(256, 3) void tgt_kernel(const float* __restrict__ tgt,
                                                     const float* __restrict__ g2,
                                                     const float* __restrict__ b2,
                                                     float* __restrict__ out2) {
    extern __shared__ char sm[];
    __half* Ws = (__half*)sm;
    __half* Xs = Ws + D * LDS_T;
    float* Cs = (float*)sm;
    int tid = threadIdx.x;
    int row0 = blockIdx.x * 64;
    load_W_cp(Ws, 3, tid);
    load_Xh_cp(Xs, g_red + (size_t)row0 * D, tid);   // fp16 rows straight into image
    cp_commit();
    cp_wait0();
    __syncthreads();
    float acc[8][4];
    gemm_mma64(Xs, Ws, tid, acc);
    __syncthreads();
    stage_acc(Cs, acc, tid);
    __syncthreads();

    int tx = tid & 31, ty = tid >> 5;
    float gg[4], bb[4];
    #pragma unroll
    for (int c = 0; c < 4; c++) { gg[c] = g2[tx * 4 + c]; bb[c] = b2[tx * 4 + c]; }
    #pragma unroll
    for (int r = 0; r < 8; r++) {
        int row = row0 + ty * 8 + r;
        float4 cv = *(float4*)(Cs + (ty * 8 + r) * LDC + tx * 4);
        uint2 pp = *(const uint2*)(g_Ptt + (size_t)row * D + tx * 4);
        __half2 p0 = *(__half2*)&pp.x, p1 = *(__half2*)&pp.y;
        float v[4];
        v[0] = cv.x + __half2float(p0.x);
        v[1] = cv.y + __half2float(p0.y);
        v[2] = cv.z + __half2float(p1.x);
        v[3] = cv.w + __half2float(p1.y);
        float d[4];
        silu_ln(v, gg, bb, d);
        float4 tin = *(const float4*)(tgt + (size_t)row * D + tx * 4);
        float4 o2 = {tin.x + d[0], tin.y + d[1], tin.z + d[2], tin.w + d[3]};
        *(float4*)(out2 + (size_t)row * D + tx * 4) = o2;
    }
}

// ---------------- launch ----------------
extern "C" void kernel_launch(void* const* d_in, const int* in_sizes, int n_in,
                              void* d_out, int out_size) {
    const float* bond  = (const float*)d_in[0];
    const float* src   = (const float*)d_in[1];
    const float* tgt   = (const float*)d_in[2];
    const float* W_s2e = (const float*)d_in[3];
    const float* W_t2e = (const float*)d_in[4];
    const float* W_e2e = (const float*)d_in[5];
    const float* ln1_g = (const float*)d_in[6];
    const float* ln1_b = (const float*)d_in[7];
    const float* W_e2t = (const float*)d_in[8];
    const float* W_t2t = (const float*)d_in[9];
    const float* ln2_g = (const float*)d_in[10];
    const float* ln2_b = (const float*)d_in[11];
    const float* coef  = (const float*)d_in[12];
    const int*   so    = (const int*)d_in[13];
    const int*   to    = (const int*)d_in[14];
    const int*   eo    = (const int*)d_in[15];

    float* out  = (float*)d_out;
    float* out0 = out;                                   // bond + d_bond   [B,E,D]
    float* out1 = out0 + (size_t)Bn * En * D;            // src passthrough [B,NS,D]
    float* out2 = out1 + (size_t)Bn * NSn * D;           // tgt + d_tgt     [B,NT,D]

    cudaFuncSetAttribute(proj_kernel, cudaFuncAttributeMaxDynamicSharedMemorySize, SM_SINGLE);
    cudaFuncSetAttribute(bond_kernel, cudaFuncAttributeMaxDynamicSharedMemorySize, SM_BOND);
    cudaFuncSetAttribute(tgt_kernel,  cudaFuncAttributeMaxDynamicSharedMemorySize, SM_SINGLE);

    prep_w_kernel<<<320, 256>>>(W_s2e, W_t2e, W_e2e, W_e2t, W_t2t);

    // three projection GEMMs + fused src passthrough
    proj_kernel<<<3 * 625, 256, SM_SINGLE>>>(src, tgt, out1);

    bond_kernel<<<(Bn * En) / 64, 256, SM_BOND>>>(bond, ln1_g, ln1_b, so, to, out0);

    reduce_kernel<<<(Bn * NTn) / 8, 256>>>(eo, coef);

    tgt_kernel<<<(Bn * NTn) / 64, 256, SM_SINGLE>>>(tgt, ln2_g, ln2_b, out2);
}

// round 17
// speedup vs baseline: 1.0953x; 1.0386x over previous
#include <cuda_runtime.h>
#include <cuda_fp16.h>
#include <math.h>
#include <stdint.h>

#define D    128
#define Bn   4
#define NSn  10000
#define NTn  10000
#define En   160000
#define Kc   16
#define LDS_T 136   // padded fp16 row (272B, 16B-aligned, ldmatrix conflict-free)
#define LDC   132   // padded C row (element count; fp16 staging)

// ---------------- scratch ----------------
__device__ __half g_Ps  [Bn * NSn * D];   // src @ W_s2e   (fp16)
__device__ __half g_Pt  [Bn * NTn * D];   // tgt @ W_t2e   (fp16)
__device__ __half g_Ptt [Bn * NTn * D];   // tgt @ W_t2t   (fp16)
__device__ __half g_db  [Bn * En  * D];   // d_bond scratch (fp16, feeds reduce only)
__device__ __half g_W[5 * D * D];   // 0=W_s2e 1=W_t2e 2=W_e2e 3=W_e2t 4=W_t2t (fp16)

// ---------------- PTX helpers ----------------
__device__ __forceinline__ uint32_t smem_u32(const void* p) {
    return (uint32_t)__cvta_generic_to_shared(p);
}
__device__ __forceinline__ void ldsm4(uint32_t a, uint32_t r[4]) {
    asm volatile("ldmatrix.sync.aligned.m8n8.x4.shared.b16 {%0,%1,%2,%3}, [%4];"
                 : "=r"(r[0]), "=r"(r[1]), "=r"(r[2]), "=r"(r[3]) : "r"(a));
}
__device__ __forceinline__ void ldsm4t(uint32_t a, uint32_t r[4]) {
    asm volatile("ldmatrix.sync.aligned.m8n8.x4.trans.shared.b16 {%0,%1,%2,%3}, [%4];"
                 : "=r"(r[0]), "=r"(r[1]), "=r"(r[2]), "=r"(r[3]) : "r"(a));
}
__device__ __forceinline__ void mma16816(float c[4], const uint32_t a[4],
                                         uint32_t b0, uint32_t b1) {
    asm volatile("mma.sync.aligned.m16n8k16.row.col.f32.f16.f16.f32 "
                 "{%0,%1,%2,%3},{%4,%5,%6,%7},{%8,%9},{%0,%1,%2,%3};"
                 : "+f"(c[0]), "+f"(c[1]), "+f"(c[2]), "+f"(c[3])
                 : "r"(a[0]), "r"(a[1]), "r"(a[2]), "r"(a[3]), "r"(b0), "r"(b1));
}
__device__ __forceinline__ void cp16(uint32_t dst, const void* src) {
    asm volatile("cp.async.cg.shared.global [%0], [%1], 16;" :: "r"(dst), "l"(src));
}
__device__ __forceinline__ void cp_commit() { asm volatile("cp.async.commit_group;"); }
__device__ __forceinline__ void cp_wait0()  { asm volatile("cp.async.wait_group 0;"); }
__device__ __forceinline__ void pref_l2(const void* p) {
    asm volatile("prefetch.global.L2 [%0];" :: "l"(p));
}
__device__ __forceinline__ float silu_f(float x) { return x / (1.0f + __expf(-x)); }

// ---------------- weight fp16 convert ----------------
__global__ __launch_bounds__(256) void prep_w_kernel(const float* __restrict__ W0,
                                                     const float* __restrict__ W1,
                                                     const float* __restrict__ W2,
                                                     const float* __restrict__ W3,
                                                     const float* __restrict__ W4) {
    int i = blockIdx.x * 256 + threadIdx.x;
    int w = i >> 14, j = i & (D * D - 1);
    const float* W = (w == 0) ? W0 : (w == 1) ? W1 : (w == 2) ? W2 : (w == 3) ? W3 : W4;
    g_W[i] = __float2half_rn(W[j]);
}

// ---------------- tile loads ----------------
__device__ __forceinline__ void load_W_cp(__half* Ws, int widx, int tid) {
    const __half* gw = g_W + widx * D * D;
    uint32_t dw = smem_u32(Ws);
    #pragma unroll
    for (int i = tid; i < D * 16; i += 256) {
        int r = i >> 4, c = (i & 15) * 8;
        cp16(dw + (uint32_t)(r * LDS_T + c) * 2, gw + r * D + c);
    }
}
// fp32 -> fp16 smem image; optional passthrough copy of the fp32 rows to `cp`
__device__ __forceinline__ void load_X_f16(__half* Xs, const float* __restrict__ Xg,
                                           float* __restrict__ cp, int tid) {
    #pragma unroll
    for (int i = tid; i < 64 * 32; i += 256) {
        int r = i >> 5, c = (i & 31) * 4;
        float4 v = *(const float4*)(Xg + (size_t)r * D + c);
        if (cp) *(float4*)(cp + (size_t)r * D + c) = v;
        __half2 a = __floats2half2_rn(v.x, v.y);
        __half2 b = __floats2half2_rn(v.z, v.w);
        *(uint32_t*)(Xs + r * LDS_T + c)     = *(uint32_t*)&a;
        *(uint32_t*)(Xs + r * LDS_T + c + 2) = *(uint32_t*)&b;
    }
}

// ---------------- fp16 single-MMA GEMM core: 64x128 tile, 8 warps (4 rg x 2 cg) ----------------
#define KOFF ((uint32_t)(16 * LDS_T * 2))

__device__ __forceinline__ void gemm_mma64(const __half* Xs, const __half* Ws,
                                           int tid, float acc[8][4]) {
    int lane = tid & 31, w = tid >> 5;
    int rg = (w & 3) * 16, cg = (w >> 2) * 64;
    #pragma unroll
    for (int i = 0; i < 8; i++)
        #pragma unroll
        for (int j = 0; j < 4; j++) acc[i][j] = 0.0f;
    int l7 = lane & 7, lm = lane >> 3;
    int a_cad = (lm >> 1) << 3;
    uint32_t aA = smem_u32(Xs + (rg + l7 + ((lm & 1) << 3)) * LDS_T + a_cad);
    int b_krow = l7 + ((lm & 1) << 3);
    uint32_t bB[4];
    #pragma unroll
    for (int nr = 0; nr < 4; nr++) {
        int col = cg + nr * 16 + a_cad;
        bB[nr] = smem_u32(Ws + b_krow * LDS_T + col);
    }
    #pragma unroll
    for (int k = 0; k < 8; k++) {
        uint32_t A[4];
        ldsm4(aA + (uint32_t)k * 32, A);
        #pragma unroll
        for (int nr = 0; nr < 4; nr++) {
            uint32_t B[4];
            ldsm4t(bB[nr] + (uint32_t)k * KOFF, B);
            mma16816(acc[2 * nr],     A, B[0], B[1]);
            mma16816(acc[2 * nr + 1], A, B[2], B[3]);
        }
    }
}

// fp16 staging: halves the smem stage/reload traffic
__device__ __forceinline__ void stage_acc_h(__half* Cs, const float acc[8][4], int tid) {
    int lane = tid & 31, w = tid >> 5;
    int rg = (w & 3) * 16, cg = (w >> 2) * 64;
    int gid = lane >> 2, tid4 = lane & 3;
    #pragma unroll
    for (int nt = 0; nt < 8; nt++) {
        int col = cg + nt * 8 + tid4 * 2;
        int row = rg + gid;
        __half2 a = __floats2half2_rn(acc[nt][0], acc[nt][1]);
        __half2 b = __floats2half2_rn(acc[nt][2], acc[nt][3]);
        *(uint32_t*)(Cs + row * LDC + col)       = *(uint32_t*)&a;
        *(uint32_t*)(Cs + (row + 8) * LDC + col) = *(uint32_t*)&b;
    }
}
__device__ __forceinline__ void silu_ln(float v[4], const float gg[4], const float bb[4],
                                        float out[4]) {
    #pragma unroll
    for (int c = 0; c < 4; c++) v[c] = silu_f(v[c]);
    float s1 = v[0] + v[1] + v[2] + v[3];
    float s2 = v[0]*v[0] + v[1]*v[1] + v[2]*v[2] + v[3]*v[3];
    #pragma unroll
    for (int o = 16; o > 0; o >>= 1) {
        s1 += __shfl_xor_sync(0xFFFFFFFFu, s1, o);
        s2 += __shfl_xor_sync(0xFFFFFFFFu, s2, o);
    }
    float m   = s1 * (1.0f / D);
    float var = fmaxf(s2 * (1.0f / D) - m * m, 0.0f);
    float rs  = rsqrtf(var + 1e-5f);
    #pragma unroll
    for (int c = 0; c < 4; c++) out[c] = (v[c] - m) * rs * gg[c] + bb[c];
}

// smem: [Ws 128x136][Xs 64x136] fp16; Cs_h (64x132 fp16) overlays Ws only
#define SM_SINGLE ((D * LDS_T + 64 * LDS_T) * 2)
// bond adds sG/sB (128 floats each) after Xs
#define SM_BOND   (SM_SINGLE + 2 * D * 4)

// ---------------- merged projection kernel: 3 GEMM jobs, fp16 outputs ----------------
// job 0: Ps = src@W_s2e (+ passthrough src->out1) ; job 1: Pt = tgt@W_t2e ; job 2: Ptt = tgt@W_t2t
__global__ __launch_bounds__(256, 3) void proj_kernel(const float* __restrict__ src,
                                                      const float* __restrict__ tgt,
                                                      float* __restrict__ out1) {
    extern __shared__ char sm[];
    __half* Ws = (__half*)sm;
    __half* Xs = Ws + D * LDS_T;
    __half* Cs = (__half*)sm;         // overlays Ws after MMA
    int tid = threadIdx.x;
    int job = blockIdx.x / 625;
    int blk = blockIdx.x - job * 625;
    const float* X = (job == 0) ? src : tgt;
    int widx = (job == 0) ? 0 : (job == 1) ? 1 : 4;
    __half* outp = (job == 0) ? g_Ps : (job == 1) ? g_Pt : g_Ptt;
    int row0 = blk * 64;
    load_W_cp(Ws, widx, tid);
    cp_commit();
    load_X_f16(Xs, X + (size_t)row0 * D,
               (job == 0) ? (out1 + (size_t)row0 * D) : (float*)0, tid);
    cp_wait0();
    __syncthreads();
    float acc[8][4];
    gemm_mma64(Xs, Ws, tid, acc);
    __syncthreads();
    stage_acc_h(Cs, acc, tid);
    __syncthreads();
    int tx = tid & 31, ty = tid >> 5;
    #pragma unroll
    for (int r = 0; r < 8; r++) {
        uint2 pk = *(uint2*)(Cs + (ty * 8 + r) * LDC + tx * 4);
        *(uint2*)(outp + (size_t)(row0 + ty * 8 + r) * D + tx * 4) = pk;
    }
}

// ---------------- kernel 3: d_bond = LN(silu(bond@W_e2e + gather(Ps) + gather(Pt))) ----------------
__global__ __launch_bounds__(256, 4) void bond_kernel(const float* __restrict__ bond,
                                                      const float* __restrict__ g1,
                                                      const float* __restrict__ b1,
                                                      const int* __restrict__ src_order,
                                                      const int* __restrict__ tgt_order,
                                                      float* __restrict__ out0) {
    extern __shared__ char sm[];
    __half* Ws = (__half*)sm;
    __half* Xs = Ws + D * LDS_T;
    float* sG = (float*)(Xs + 64 * LDS_T);
    float* sB = sG + D;
    __half* Cs = (__half*)sm;         // overlays Ws only; Xs/sG/sB stay live
    int tid = threadIdx.x;
    int tx = tid & 31, ty = tid >> 5;
    int row0 = blockIdx.x * 64;           // global row in [0, B*E)
    int b    = row0 / En;                 // tile never crosses batch (E % 64 == 0)
    int ebase = row0 - b * En;
    const __half* PsB = g_Ps + (size_t)b * NSn * D;
    const __half* PtB = g_Pt + (size_t)b * NTn * D;

    load_W_cp(Ws, 2, tid);                // W_e2e (async)
    cp_commit();
    load_X_f16(Xs, bond + (size_t)row0 * D, (float*)0, tid);
    if (tid < D) { sG[tid] = g1[tid]; sB[tid] = b1[tid]; }

    // pre-MMA: prefetch Ps/Pt gather sectors into L2 (fp16 rows = 2 x 128B sectors)
    {
        int rr = tx >> 2;                 // 8 rows per warp
        int h  = (tx & 1) * 64;           // 2 sectors of 64 halves
        int e = ebase + ty * 8 + rr;
        if (tx & 2) pref_l2(PtB + (size_t)tgt_order[e] * D + h);
        else        pref_l2(PsB + (size_t)src_order[e] * D + h);
    }

    cp_wait0();
    __syncthreads();
    float acc[8][4];
    gemm_mma64(Xs, Ws, tid, acc);
    __syncthreads();
    stage_acc_h(Cs, acc, tid);
    __syncthreads();

    #pragma unroll
    for (int r = 0; r < 8; r++) {
        int row = row0 + ty * 8 + r;
        int e   = ebase + ty * 8 + r;
        int so  = src_order[e];
        int to  = tgt_order[e];
        uint2 cvk = *(uint2*)(Cs + (ty * 8 + r) * LDC + tx * 4);
        __half2 c0 = *(__half2*)&cvk.x, c1 = *(__half2*)&cvk.y;
        uint2 pp = *(const uint2*)(PsB + (size_t)so * D + tx * 4);
        uint2 qq = *(const uint2*)(PtB + (size_t)to * D + tx * 4);
        __half2 p0 = *(__half2*)&pp.x, p1 = *(__half2*)&pp.y;
        __half2 q0 = *(__half2*)&qq.x, q1 = *(__half2*)&qq.y;
        float v[4];
        v[0] = __half2float(c0.x) + __half2float(p0.x) + __half2float(q0.x);
        v[1] = __half2float(c0.y) + __half2float(p0.y) + __half2float(q0.y);
        v[2] = __half2float(c1.x) + __half2float(p1.x) + __half2float(q1.x);
        v[3] = __half2float(c1.y) + __half2float(p1.y) + __half2float(q1.y);
        float gg[4] = {sG[tx * 4], sG[tx * 4 + 1], sG[tx * 4 + 2], sG[tx * 4 + 3]};
        float bb[4] = {sB[tx * 4], sB[tx * 4 + 1], sB[tx * 4 + 2], sB[tx * 4 + 3]};
        float d[4];
        silu_ln(v, gg, bb, d);
        // x for the residual read back from the fp16 smem image (no DRAM re-read)
        __half2 x01 = *(const __half2*)(Xs + (ty * 8 + r) * LDS_T + tx * 4);
        __half2 x23 = *(const __half2*)(Xs + (ty * 8 + r) * LDS_T + tx * 4 + 2);
        float4 o0 = {__half2float(x01.x) + d[0], __half2float(x01.y) + d[1],
                     __half2float(x23.x) + d[2], __half2float(x23.y) + d[3]};
        __half2 d01 = __floats2half2_rn(d[0], d[1]);
        __half2 d23 = __floats2half2_rn(d[2], d[3]);
        uint2 dpk = make_uint2(*(uint32_t*)&d01, *(uint32_t*)&d23);
        *(uint2*)(g_db + (size_t)row * D + tx * 4) = dpk;
        *(float4*)(out0 + (size_t)row * D + tx * 4) = o0;
    }
}

// ---------------- kernel 5 (fused reduce + tgt GEMM) ----------------
// phase 1: 8 warps gather-reduce 64 nodes -> fp16 Xs image (warp-per-node pattern)
// phase 2: GEMM red@W_e2t ; epilogue silu+LN ; out2 = tgt + d_tgt
__global__ __launch_bounds__(256, 3) void tgt_kernel(const float* __restrict__ tgt,
                                                     const int* __restrict__ edge_order,
                                                     const float* __restrict__ coef,
                                                     const float* __restrict__ g2,
                                                     const float* __restrict__ b2,
                                                     float* __restrict__ out2) {
    extern __shared__ char sm[];
    __half* Ws = (__half*)sm;
    __half* Xs = Ws + D * LDS_T;
    __half* Cs = (__half*)sm;
    int tid = threadIdx.x, lane = tid & 31, wid = tid >> 5;
    int row0 = blockIdx.x * 64;           // node rows [row0, row0+64)
    load_W_cp(Ws, 3, tid);
    cp_commit();

    // phase 1: gather-reduce, 8 nodes per warp, straight into the Xs image
    #pragma unroll
    for (int i = 0; i < 8; i++) {
        int node = row0 + wid * 8 + i;
        int b = node / NTn;
        int t = node - b * NTn;
        int   e_l = 0;
        float c_l = 0.0f;
        if (lane < Kc) {
            e_l = edge_order[t * Kc + lane];
            c_l = coef[t * Kc + lane];
        }
        float4 acc4 = {0.f, 0.f, 0.f, 0.f};
        #pragma unroll
        for (int k = 0; k < Kc; k++) {
            int   e = __shfl_sync(0xFFFFFFFFu, e_l, k);
            float c = __shfl_sync(0xFFFFFFFFu, c_l, k);
            uint2 pk = *(const uint2*)(g_db + ((size_t)b * En + e) * D + lane * 4);
            __half2 h0 = *(__half2*)&pk.x;
            __half2 h1 = *(__half2*)&pk.y;
            acc4.x += c * __half2float(h0.x);
            acc4.y += c * __half2float(h0.y);
            acc4.z += c * __half2float(h1.x);
            acc4.w += c * __half2float(h1.y);
        }
        const float inv = 1.0f / Kc;
        __half2 r01 = __floats2half2_rn(acc4.x * inv, acc4.y * inv);
        __half2 r23 = __floats2half2_rn(acc4.z * inv, acc4.w * inv);
        __half* xr = Xs + (wid * 8 + i) * LDS_T + lane * 4;
        *(uint32_t*)(xr)     = *(uint32_t*)&r01;
        *(uint32_t*)(xr + 2) = *(uint32_t*)&r23;
    }

    cp_wait0();
    __syncthreads();
    float acc[8][4];
    gemm_mma64(Xs, Ws, tid, acc);
    __syncthreads();
    stage_acc_h(Cs, acc, tid);
    __syncthreads();

    int tx = tid & 31, ty = tid >> 5;
    float gg[4], bb[4];
    #pragma unroll
    for (int c = 0; c < 4; c++) { gg[c] = g2[tx * 4 + c]; bb[c] = b2[tx * 4 + c]; }
    #pragma unroll
    for (int r = 0; r < 8; r++) {
        int row = row0 + ty * 8 + r;
        uint2 cvk = *(uint2*)(Cs + (ty * 8 + r) * LDC + tx * 4);
        __half2 c0 = *(__half2*)&cvk.x, c1 = *(__half2*)&cvk.y;
        uint2 pp = *(const uint2*)(g_Ptt + (size_t)row * D + tx * 4);
        __half2 p0 = *(__half2*)&pp.x, p1 = *(__half2*)&pp.y;
        float v[4];
        v[0] = __half2float(c0.x) + __half2float(p0.x);
        v[1] = __half2float(c0.y) + __half2float(p0.y);
        v[2] = __half2float(c1.x) + __half2float(p1.x);
        v[3] = __half2float(c1.y) + __half2float(p1.y);
        float d[4];
        silu_ln(v, gg, bb, d);
        float4 tin = *(const float4*)(tgt + (size_t)row * D + tx * 4);
        float4 o2 = {tin.x + d[0], tin.y + d[1], tin.z + d[2], tin.w + d[3]};
        *(float4*)(out2 + (size_t)row * D + tx * 4) = o2;
    }
}

// ---------------- launch ----------------
extern "C" void kernel_launch(void* const* d_in, const int* in_sizes, int n_in,
                              void* d_out, int out_size) {
    const float* bond  = (const float*)d_in[0];
    const float* src   = (const float*)d_in[1];
    const float* tgt   = (const float*)d_in[2];
    const float* W_s2e = (const float*)d_in[3];
    const float* W_t2e = (const float*)d_in[4];
    const float* W_e2e = (const float*)d_in[5];
    const float* ln1_g = (const float*)d_in[6];
    const float* ln1_b = (const float*)d_in[7];
    const float* W_e2t = (const float*)d_in[8];
    const float* W_t2t = (const float*)d_in[9];
    const float* ln2_g = (const float*)d_in[10];
    const float* ln2_b = (const float*)d_in[11];
    const float* coef  = (const float*)d_in[12];
    const int*   so    = (const int*)d_in[13];
    const int*   to    = (const int*)d_in[14];
    const int*   eo    = (const int*)d_in[15];

    float* out  = (float*)d_out;
    float* out0 = out;                                   // bond + d_bond   [B,E,D]
    float* out1 = out0 + (size_t)Bn * En * D;            // src passthrough [B,NS,D]
    float* out2 = out1 + (size_t)Bn * NSn * D;           // tgt + d_tgt     [B,NT,D]

    cudaFuncSetAttribute(proj_kernel, cudaFuncAttributeMaxDynamicSharedMemorySize, SM_SINGLE);
    cudaFuncSetAttribute(bond_kernel, cudaFuncAttributeMaxDynamicSharedMemorySize, SM_BOND);
    cudaFuncSetAttribute(tgt_kernel,  cudaFuncAttributeMaxDynamicSharedMemorySize, SM_SINGLE);

    prep_w_kernel<<<320, 256>>>(W_s2e, W_t2e, W_e2e, W_e2t, W_t2t);

    // three projection GEMMs + fused src passthrough
    proj_kernel<<<3 * 625, 256, SM_SINGLE>>>(src, tgt, out1);

    bond_kernel<<<(Bn * En) / 64, 256, SM_BOND>>>(bond, ln1_g, ln1_b, so, to, out0);

    // fused bond_reduce + target update
    tgt_kernel<<<(Bn * NTn) / 64, 256, SM_SINGLE>>>(tgt, eo, coef, ln2_g, ln2_b, out2);
}